// round 3
// baseline (speedup 1.0000x reference)
#include <cuda_runtime.h>

#define TSTEPS  1024
#define BATCH   64
#define IN_DIM  256
#define HID_DIM 512
#define OUT_DIM 256
#define KDIM    768
#define NCTA    128
#define NTHR    768

// ---- device-wide barrier state (graph-replay safe: count self-resets) ----
__device__ unsigned g_bar_count = 0;
__device__ volatile unsigned g_bar_gen = 0;

__device__ __forceinline__ void grid_barrier() {
    __syncthreads();
    if (threadIdx.x == 0) {
        __threadfence();                       // release my writes
        unsigned g = g_bar_gen;                // read gen BEFORE arriving
        if (atomicAdd(&g_bar_count, 1u) == NCTA - 1) {
            g_bar_count = 0;
            __threadfence();                   // reset ordered before gen bump
            g_bar_gen = g + 1;
        } else {
            while (g_bar_gen == g) {}
            __threadfence();                   // acquire others' writes
        }
    }
    __syncthreads();
}

// packed f32x2 FMA: d.lo += a.lo*b.lo ; d.hi += a.hi*b.hi  (sm_100+)
__device__ __forceinline__ void ffma2(unsigned long long& d,
                                      unsigned long long a,
                                      unsigned long long b) {
    asm("fma.rn.f32x2 %0, %1, %2, %0;" : "+l"(d) : "l"(a), "l"(b));
}
__device__ __forceinline__ float merge2(unsigned long long v) {
    float lo, hi;
    asm("mov.b64 {%0, %1}, %2;" : "=f"(lo), "=f"(hi) : "l"(v));
    return lo + hi;
}

// Persistent RNN kernel, v3.
// 128 CTAs = 64 column-groups x 2 batch-halves. CTA = 768 threads = 24 warps.
//   column-group g owns h-cols [g*8,g*8+8) and r-cols [g*4,g*4+4)
//   warp = (col-set cs in {0,1,2}) x (batch-oct, 4 rows)
//     cs 0: h-cols jh0+0..3   cs 1: h-cols jh0+4..7   cs 2: r-cols jr0+0..3
//   lane = k-slice (k = 4*lane + 128*i). Accumulators are f32x2 (k-parity split).
// One grid barrier per iteration. The x-dot for step it+1 is computed BEFORE
// the barrier (X is a pure input) so its LDG latency hides under the spin.
__global__ void __launch_bounds__(NTHR, 1)
rnn_persistent_kernel(const float* __restrict__ X,    // [64][1024][256]
                      const float* __restrict__ H0,   // [64][512]
                      const float* __restrict__ R0,   // [64][256]
                      const float* __restrict__ Wih,  // [512][768]
                      const float* __restrict__ Bih,  // [512]
                      const float* __restrict__ Who,  // [256][768]
                      const float* __restrict__ Bho,  // [256]
                      float* __restrict__ Rout,       // [64][1025][256]
                      float* __restrict__ Hout)       // [64][1025][512]
{
    __shared__ float W1s[8][KDIM];   // W_ih rows jh0..jh0+7 (k: 0..255 x | 256..767 h)
    __shared__ float W2s[4][KDIM];   // W_ho rows jr0..jr0+3 (k: 0..511 h | 512..767 r)
    __shared__ float bih_s[8];
    __shared__ float bho_s[4];

    const int tid  = threadIdx.x;
    const int cta  = blockIdx.x;
    const int grp  = cta >> 1;
    const int half = cta & 1;
    const int b0   = half * 32;
    const int jh0  = grp * 8;
    const int jr0  = grp * 4;
    const int wrp  = tid >> 5;
    const int lane = tid & 31;
    const int cs   = wrp >> 3;        // 0,1: h-col quads; 2: r-col quad
    const int boct = wrp & 7;
    const int bb0  = b0 + boct * 4;

    // ---- stationary weight slices -> smem ----
    for (int idx = tid; idx < 8 * KDIM; idx += NTHR) {
        int j = idx / KDIM, k = idx % KDIM;
        W1s[j][k] = Wih[(jh0 + j) * KDIM + k];
    }
    for (int idx = tid; idx < 4 * KDIM; idx += NTHR) {
        int j = idx / KDIM, k = idx % KDIM;
        W2s[j][k] = Who[(jr0 + j) * KDIM + k];
    }
    if (tid < 8) bih_s[tid] = Bih[jh0 + tid];
    if (tid < 4) bho_s[tid] = Bho[jr0 + tid];

    // ---- t=0 states into output/exchange buffers ----
    for (int idx = tid; idx < 32 * 8; idx += NTHR) {
        int b = b0 + (idx >> 3), jj = idx & 7;
        Hout[(size_t)(b * 1025) * HID_DIM + jh0 + jj] = H0[b * HID_DIM + jh0 + jj];
    }
    for (int idx = tid; idx < 32 * 4; idx += NTHR) {
        int b = b0 + (idx >> 2), jj = idx & 3;
        Rout[(size_t)(b * 1025) * OUT_DIM + jr0 + jj] = R0[b * OUT_DIM + jr0 + jj];
    }
    __syncthreads();   // smem weights ready for pre-barrier x-dot below

    // A2[b*4+c]: f32x2 accumulator for (batch bb0+b, col c of this warp's set)
    unsigned long long A2[16];
#pragma unroll
    for (int i = 0; i < 16; ++i) A2[i] = 0ull;

    // ---- prologue: x-dot for it=0 (h-col warps only) ----
    if (cs < 2) {
#pragma unroll
        for (int i = 0; i < 2; ++i) {
            const int k = 4 * lane + 128 * i;
            unsigned long long w[4][2];
#pragma unroll
            for (int c = 0; c < 4; ++c) {
                const ulonglong2 wv = *(const ulonglong2*)&W1s[cs * 4 + c][k];
                w[c][0] = wv.x; w[c][1] = wv.y;
            }
#pragma unroll
            for (int b = 0; b < 4; ++b) {
                const ulonglong2 a = *(const ulonglong2*)&X[((size_t)(bb0 + b) * TSTEPS + 0) * IN_DIM + k];
#pragma unroll
                for (int c = 0; c < 4; ++c) {
                    ffma2(A2[b * 4 + c], a.x, w[c][0]);
                    ffma2(A2[b * 4 + c], a.y, w[c][1]);
                }
            }
        }
    }

    grid_barrier();

    for (int it = 0; it <= TSTEPS; ++it) {
        // ---- recurrent part: h[it] -> (h-dot | r-dot), r[it-1] -> r-dot ----
#pragma unroll
        for (int i = 0; i < 4; ++i) {
            const int hk = 4 * lane + 128 * i;   // 0..511
            unsigned long long w[4][2];
#pragma unroll
            for (int c = 0; c < 4; ++c) {
                const float* wp = (cs < 2) ? &W1s[cs * 4 + c][256 + hk] : &W2s[c][hk];
                const ulonglong2 wv = *(const ulonglong2*)wp;
                w[c][0] = wv.x; w[c][1] = wv.y;
            }
#pragma unroll
            for (int b = 0; b < 4; ++b) {
                const ulonglong2 a = *(const ulonglong2*)&Hout[((size_t)(bb0 + b) * 1025 + it) * HID_DIM + hk];
#pragma unroll
                for (int c = 0; c < 4; ++c) {
                    ffma2(A2[b * 4 + c], a.x, w[c][0]);
                    ffma2(A2[b * 4 + c], a.y, w[c][1]);
                }
            }
        }
        if (cs == 2 && it >= 1) {
#pragma unroll
            for (int i = 0; i < 2; ++i) {
                const int rk = 4 * lane + 128 * i;   // 0..255
                unsigned long long w[4][2];
#pragma unroll
                for (int c = 0; c < 4; ++c) {
                    const ulonglong2 wv = *(const ulonglong2*)&W2s[c][512 + rk];
                    w[c][0] = wv.x; w[c][1] = wv.y;
                }
#pragma unroll
                for (int b = 0; b < 4; ++b) {
                    const ulonglong2 a = *(const ulonglong2*)&Rout[((size_t)(bb0 + b) * 1025 + (it - 1)) * OUT_DIM + rk];
#pragma unroll
                    for (int c = 0; c < 4; ++c) {
                        ffma2(A2[b * 4 + c], a.x, w[c][0]);
                        ffma2(A2[b * 4 + c], a.y, w[c][1]);
                    }
                }
            }
        }

        // ---- merge parity halves, transpose-butterfly (lane L keeps output L) ----
        float S[16];
#pragma unroll
        for (int i = 0; i < 16; ++i) S[i] = merge2(A2[i]);
#pragma unroll
        for (int off = 16; off >= 1; off >>= 1) {
#pragma unroll
            for (int i = 0; i < off && i < 16; ++i) {
                const int j = i + off;
                const float vj = (j < 16) ? S[j] : 0.f;
                const float send = (lane & off) ? S[i] : vj;
                const float recv = __shfl_xor_sync(0xffffffffu, send, off);
                const float keep = (lane & off) ? vj : S[i];
                S[i] = keep + recv;
            }
        }

        // ---- bias + relu + store ----
        if (lane < 16) {
            const int b = lane >> 2, c = lane & 3;
            if (cs < 2) {
                if (it < TSTEPS) {
                    const float v = fmaxf(S[0] + bih_s[cs * 4 + c], 0.f);
                    Hout[((size_t)(bb0 + b) * 1025 + (it + 1)) * HID_DIM + jh0 + cs * 4 + c] = v;
                }
            } else {
                if (it >= 1) {
                    const float v = fmaxf(S[0] + bho_s[c], 0.f);
                    Rout[((size_t)(bb0 + b) * 1025 + it) * OUT_DIM + jr0 + c] = v;
                }
            }
        }

        // ---- pre-barrier: zero accs and fold in x-dot for it+1 ----
#pragma unroll
        for (int i = 0; i < 16; ++i) A2[i] = 0ull;
        if (cs < 2 && it + 1 < TSTEPS) {
            const int xt = it + 1;
#pragma unroll
            for (int i = 0; i < 2; ++i) {
                const int k = 4 * lane + 128 * i;
                unsigned long long w[4][2];
#pragma unroll
                for (int c = 0; c < 4; ++c) {
                    const ulonglong2 wv = *(const ulonglong2*)&W1s[cs * 4 + c][k];
                    w[c][0] = wv.x; w[c][1] = wv.y;
                }
#pragma unroll
                for (int b = 0; b < 4; ++b) {
                    const ulonglong2 a = *(const ulonglong2*)&X[((size_t)(bb0 + b) * TSTEPS + xt) * IN_DIM + k];
#pragma unroll
                    for (int c = 0; c < 4; ++c) {
                        ffma2(A2[b * 4 + c], a.x, w[c][0]);
                        ffma2(A2[b * 4 + c], a.y, w[c][1]);
                    }
                }
            }
        }

        grid_barrier();
    }
}

extern "C" void kernel_launch(void* const* d_in, const int* in_sizes, int n_in,
                              void* d_out, int out_size) {
    const float* X   = (const float*)d_in[0];
    const float* H0  = (const float*)d_in[1];
    const float* R0  = (const float*)d_in[2];
    const float* Wih = (const float*)d_in[3];
    const float* Bih = (const float*)d_in[4];
    const float* Who = (const float*)d_in[5];
    const float* Bho = (const float*)d_in[6];

    float* Rout = (float*)d_out;                                   // [64][1025][256]
    float* Hout = (float*)d_out + (size_t)BATCH * 1025 * OUT_DIM;  // [64][1025][512]

    rnn_persistent_kernel<<<NCTA, NTHR>>>(X, H0, R0, Wih, Bih, Who, Bho, Rout, Hout);
}

// round 4
// speedup vs baseline: 1.4304x; 1.4304x over previous
#include <cuda_runtime.h>

#define TSTEPS  1024
#define BATCH   64
#define IN_DIM  256
#define HID_DIM 512
#define OUT_DIM 256
#define KDIM    768
#define NCTA    128
#define NTHR    512

// smem: W1s[16][768] + W2s[8][768] + biases
#define W1_ROWS 16
#define W2_ROWS 8
#define SMEM_FLOATS (W1_ROWS * KDIM + W2_ROWS * KDIM + W1_ROWS + W2_ROWS)

// ---- device-wide barrier state (graph-replay safe: count self-resets) ----
__device__ unsigned g_bar_count = 0;
__device__ volatile unsigned g_bar_gen = 0;

__device__ __forceinline__ void grid_barrier() {
    __syncthreads();
    if (threadIdx.x == 0) {
        __threadfence();                       // release my writes
        unsigned g = g_bar_gen;                // read gen BEFORE arriving
        if (atomicAdd(&g_bar_count, 1u) == NCTA - 1) {
            g_bar_count = 0;
            __threadfence();                   // reset ordered before gen bump
            g_bar_gen = g + 1;
        } else {
            while (g_bar_gen == g) {}
            __threadfence();                   // acquire others' writes
        }
    }
    __syncthreads();
}

// Persistent RNN kernel, v4.
// 128 CTAs = 32 column-groups x 4 batch-quads. CTA = 512 threads = 16 warps.
//   column-group g owns h-cols [g*16,g*16+16) and r-cols [g*8,g*8+8)
//   batch-quad q owns rows [q*16, q*16+16)
//   warp = (col-part cp in 0..3) x (sub-quad bq, 4 rows)
//     cp owns 4 h-cols (g*16+cp*4..) and 2 r-cols (g*8+cp*2..)
//   lane = k-slice (k = 4*lane + 128*i), float4 operands, plain FFMA.
// One grid barrier per iteration. The x-dot for step it+1 runs BEFORE the
// barrier (X is a pure input) so its LDG latency hides under the spin.
// vs v2: h/r/X L2 re-read redundancy halved (32 col-group CTAs per element
// instead of 64).
__global__ void __launch_bounds__(NTHR, 1)
rnn_persistent_kernel(const float* __restrict__ X,    // [64][1024][256]
                      const float* __restrict__ H0,   // [64][512]
                      const float* __restrict__ R0,   // [64][256]
                      const float* __restrict__ Wih,  // [512][768]
                      const float* __restrict__ Bih,  // [512]
                      const float* __restrict__ Who,  // [256][768]
                      const float* __restrict__ Bho,  // [256]
                      float* __restrict__ Rout,       // [64][1025][256]
                      float* __restrict__ Hout)       // [64][1025][512]
{
    extern __shared__ float smem[];
    float* W1s   = smem;                        // [16][768]
    float* W2s   = smem + W1_ROWS * KDIM;       // [8][768]
    float* bih_s = W2s + W2_ROWS * KDIM;        // [16]
    float* bho_s = bih_s + W1_ROWS;             // [8]

    const int tid  = threadIdx.x;
    const int cta  = blockIdx.x;
    const int grp  = cta >> 2;        // 0..31 column group
    const int quad = cta & 3;         // 0..3 batch quad
    const int b0   = quad * 16;
    const int jh0  = grp * 16;
    const int jr0  = grp * 8;
    const int wrp  = tid >> 5;
    const int lane = tid & 31;
    const int cp   = wrp >> 2;        // 0..3 col part (4 h + 2 r cols)
    const int bq   = wrp & 3;         // sub-quad (4 rows)
    const int bb0  = b0 + bq * 4;

    // ---- stationary weight slices -> smem (coalesced over k) ----
    for (int idx = tid; idx < W1_ROWS * KDIM; idx += NTHR) {
        int j = idx / KDIM, k = idx - j * KDIM;
        W1s[idx] = Wih[(jh0 + j) * KDIM + k];
    }
    for (int idx = tid; idx < W2_ROWS * KDIM; idx += NTHR) {
        int j = idx / KDIM, k = idx - j * KDIM;
        W2s[idx] = Who[(jr0 + j) * KDIM + k];
    }
    if (tid < W1_ROWS) bih_s[tid] = Bih[jh0 + tid];
    if (tid < W2_ROWS) bho_s[tid] = Bho[jr0 + tid];

    // ---- t=0 states into output/exchange buffers ----
    for (int idx = tid; idx < 16 * 16; idx += NTHR) {
        int b = b0 + (idx >> 4), jj = idx & 15;
        Hout[(size_t)(b * 1025) * HID_DIM + jh0 + jj] = H0[b * HID_DIM + jh0 + jj];
    }
    for (int idx = tid; idx < 16 * 8; idx += NTHR) {
        int b = b0 + (idx >> 3), jj = idx & 7;
        Rout[(size_t)(b * 1025) * OUT_DIM + jr0 + jj] = R0[b * OUT_DIM + jr0 + jj];
    }
    __syncthreads();   // smem weights ready for the prologue x-dot

    // A[b*6+c]: c 0..3 = h-col (jh0 + cp*4 + c), c 4..5 = r-col (jr0 + cp*2 + c-4)
    float A[24];
#pragma unroll
    for (int i = 0; i < 24; ++i) A[i] = 0.f;

    const float* W1p = &W1s[(cp * 4) * KDIM];   // this warp's 4 h-col rows
    const float* W2p = &W2s[(cp * 2) * KDIM];   // this warp's 2 r-col rows

    // ---- prologue: x-dot for it=0 ----
#pragma unroll
    for (int i = 0; i < 2; ++i) {
        const int k = 4 * lane + 128 * i;
        float4 w[4];
#pragma unroll
        for (int c = 0; c < 4; ++c) w[c] = *(const float4*)&W1p[c * KDIM + k];
#pragma unroll
        for (int b = 0; b < 4; ++b) {
            const float4 a = *(const float4*)&X[((size_t)(bb0 + b) * TSTEPS + 0) * IN_DIM + k];
#pragma unroll
            for (int c = 0; c < 4; ++c)
                A[b * 6 + c] += a.x * w[c].x + a.y * w[c].y
                              + a.z * w[c].z + a.w * w[c].w;
        }
    }

    grid_barrier();

    for (int it = 0; it <= TSTEPS; ++it) {
        // ---- h[it] feeds BOTH the h-dot (W_ih k=256..767) and r-dot (W_ho k=0..511) ----
#pragma unroll
        for (int i = 0; i < 4; ++i) {
            const int hk = 4 * lane + 128 * i;   // 0..511
            float4 w1[4], w2[2];
#pragma unroll
            for (int c = 0; c < 4; ++c) w1[c] = *(const float4*)&W1p[c * KDIM + 256 + hk];
#pragma unroll
            for (int c = 0; c < 2; ++c) w2[c] = *(const float4*)&W2p[c * KDIM + hk];
#pragma unroll
            for (int b = 0; b < 4; ++b) {
                const float4 a = *(const float4*)&Hout[((size_t)(bb0 + b) * 1025 + it) * HID_DIM + hk];
#pragma unroll
                for (int c = 0; c < 4; ++c)
                    A[b * 6 + c] += a.x * w1[c].x + a.y * w1[c].y
                                  + a.z * w1[c].z + a.w * w1[c].w;
#pragma unroll
                for (int c = 0; c < 2; ++c)
                    A[b * 6 + 4 + c] += a.x * w2[c].x + a.y * w2[c].y
                                      + a.z * w2[c].z + a.w * w2[c].w;
            }
        }

        // ---- r[it-1] contribution (W_ho k = 512..767) ----
        if (it >= 1) {
#pragma unroll
            for (int i = 0; i < 2; ++i) {
                const int rk = 4 * lane + 128 * i;   // 0..255
                float4 w2[2];
#pragma unroll
                for (int c = 0; c < 2; ++c) w2[c] = *(const float4*)&W2p[c * KDIM + 512 + rk];
#pragma unroll
                for (int b = 0; b < 4; ++b) {
                    const float4 a = *(const float4*)&Rout[((size_t)(bb0 + b) * 1025 + (it - 1)) * OUT_DIM + rk];
#pragma unroll
                    for (int c = 0; c < 2; ++c)
                        A[b * 6 + 4 + c] += a.x * w2[c].x + a.y * w2[c].y
                                          + a.z * w2[c].z + a.w * w2[c].w;
                }
            }
        }

        // ---- transpose-butterfly reduction: 31 shuffles, output L lands on lane L ----
#pragma unroll
        for (int off = 16; off >= 1; off >>= 1) {
#pragma unroll
            for (int i = 0; i < off && i < 24; ++i) {
                const int j = i + off;
                const float vj = (j < 24) ? A[j] : 0.f;
                const float send = (lane & off) ? A[i] : vj;
                const float recv = __shfl_xor_sync(0xffffffffu, send, off);
                const float keep = (lane & off) ? vj : A[i];
                A[i] = keep + recv;
            }
        }

        // ---- bias + relu + store (lane L holds flat output L) ----
        if (lane < 24) {
            const int bl = lane / 6;
            const int c  = lane % 6;
            if (c < 4) {
                if (it < TSTEPS) {
                    const float v = fmaxf(A[0] + bih_s[cp * 4 + c], 0.f);
                    Hout[((size_t)(bb0 + bl) * 1025 + (it + 1)) * HID_DIM + jh0 + cp * 4 + c] = v;
                }
            } else {
                if (it >= 1) {
                    const int cc = c - 4;
                    const float v = fmaxf(A[0] + bho_s[cp * 2 + cc], 0.f);
                    Rout[((size_t)(bb0 + bl) * 1025 + it) * OUT_DIM + jr0 + cp * 2 + cc] = v;
                }
            }
        }

        // ---- pre-barrier: zero accs and fold in x-dot for it+1 (hides X latency) ----
#pragma unroll
        for (int i = 0; i < 24; ++i) A[i] = 0.f;
        if (it + 1 < TSTEPS) {
            const int xt = it + 1;
#pragma unroll
            for (int i = 0; i < 2; ++i) {
                const int k = 4 * lane + 128 * i;
                float4 w[4];
#pragma unroll
                for (int c = 0; c < 4; ++c) w[c] = *(const float4*)&W1p[c * KDIM + k];
#pragma unroll
                for (int b = 0; b < 4; ++b) {
                    const float4 a = *(const float4*)&X[((size_t)(bb0 + b) * TSTEPS + xt) * IN_DIM + k];
#pragma unroll
                    for (int c = 0; c < 4; ++c)
                        A[b * 6 + c] += a.x * w[c].x + a.y * w[c].y
                                      + a.z * w[c].z + a.w * w[c].w;
                }
            }
        }

        grid_barrier();
    }
}

extern "C" void kernel_launch(void* const* d_in, const int* in_sizes, int n_in,
                              void* d_out, int out_size) {
    const float* X   = (const float*)d_in[0];
    const float* H0  = (const float*)d_in[1];
    const float* R0  = (const float*)d_in[2];
    const float* Wih = (const float*)d_in[3];
    const float* Bih = (const float*)d_in[4];
    const float* Who = (const float*)d_in[5];
    const float* Bho = (const float*)d_in[6];

    float* Rout = (float*)d_out;                                   // [64][1025][256]
    float* Hout = (float*)d_out + (size_t)BATCH * 1025 * OUT_DIM;  // [64][1025][512]

    static int smem_set = 0;
    const int smem_bytes = SMEM_FLOATS * (int)sizeof(float);
    if (!smem_set) {
        cudaFuncSetAttribute(rnn_persistent_kernel,
                             cudaFuncAttributeMaxDynamicSharedMemorySize, smem_bytes);
        smem_set = 1;
    }
    rnn_persistent_kernel<<<NCTA, NTHR, smem_bytes>>>(X, H0, R0, Wih, Bih, Who, Bho,
                                                      Rout, Hout);
}

// round 5
// speedup vs baseline: 1.9161x; 1.3395x over previous
#include <cuda_runtime.h>

#define TSTEPS  1024
#define BATCH   64
#define IN_DIM  256
#define HID_DIM 512
#define OUT_DIM 256
#define KDIM    768
#define NCTA    128
#define NTHR    512

// ---- global-barrier state (used twice: init + pre-reset; sense-reversing) ----
__device__ unsigned g_bar_count = 0;
__device__ volatile unsigned g_bar_gen = 0;

// ---- per-half monotonic epoch counters (padded to separate 256B L2 sectors) ----
// zero at launch start (reset at end of previous launch behind the final barrier)
__device__ unsigned g_cnt[2 * 64];

__device__ __forceinline__ void grid_barrier() {
    __syncthreads();
    if (threadIdx.x == 0) {
        __threadfence();
        unsigned g = g_bar_gen;
        if (atomicAdd(&g_bar_count, 1u) == NCTA - 1) {
            g_bar_count = 0;
            __threadfence();
            g_bar_gen = g + 1;
        } else {
            while (g_bar_gen == g) {}
            __threadfence();
        }
    }
    __syncthreads();
}

__device__ __forceinline__ void red_release_add1(unsigned* p) {
    asm volatile("red.release.gpu.add.u32 [%0], 1;" :: "l"(p) : "memory");
}
__device__ __forceinline__ unsigned ld_acquire_u32(const unsigned* p) {
    unsigned v;
    asm volatile("ld.acquire.gpu.u32 %0, [%1];" : "=r"(v) : "l"(p) : "memory");
    return v;
}

// Persistent RNN kernel, v5 = v2 compute body + lightweight half-barriers.
// 128 CTAs = 64 column-groups x 2 batch-halves. CTA = 512 threads = 16 warps.
//   column-group g owns h-cols [g*8,g*8+8) and r-cols [g*4,g*4+4)
//   warp = (col-half ch) x (batch-oct, 4 rows); warp computes 4 h-cols + 2 r-cols.
//   lane = k-slice (k = 4*lane + 128*i), float4, plain FFMA.
// Sync per iteration: red.release on this half's epoch counter; thread 0 polls
// with ld.acquire until cnt >= 64*(it+1), relays through a volatile smem flag.
// The x-dot for it+1 is computed between arrival and release detection.
__global__ void __launch_bounds__(NTHR, 1)
rnn_persistent_kernel(const float* __restrict__ X,    // [64][1024][256]
                      const float* __restrict__ H0,   // [64][512]
                      const float* __restrict__ R0,   // [64][256]
                      const float* __restrict__ Wih,  // [512][768]
                      const float* __restrict__ Bih,  // [512]
                      const float* __restrict__ Who,  // [256][768]
                      const float* __restrict__ Bho,  // [256]
                      float* __restrict__ Rout,       // [64][1025][256]
                      float* __restrict__ Hout)       // [64][1025][512]
{
    __shared__ float W1s[8][KDIM];   // W_ih rows jh0.. (k: 0..255 x | 256..767 h)
    __shared__ float W2s[4][KDIM];   // W_ho rows jr0.. (k: 0..511 h | 512..767 r)
    __shared__ float bih_s[8];
    __shared__ float bho_s[4];
    volatile __shared__ int bar_flag;

    const int tid  = threadIdx.x;
    const int cta  = blockIdx.x;
    const int grp  = cta >> 1;
    const int half = cta & 1;
    const int b0   = half * 32;
    const int jh0  = grp * 8;
    const int jr0  = grp * 4;
    const int wrp  = tid >> 5;
    const int lane = tid & 31;
    const int ch   = wrp >> 3;        // col half: 4 h-cols + 2 r-cols
    const int boct = wrp & 7;
    const int bb0  = b0 + boct * 4;
    unsigned* cnt  = &g_cnt[half * 64];

    // ---- stationary weight slices -> smem ----
    for (int idx = tid; idx < 8 * KDIM; idx += NTHR) {
        int j = idx / KDIM, k = idx - j * KDIM;
        W1s[j][k] = Wih[(jh0 + j) * KDIM + k];
    }
    for (int idx = tid; idx < 4 * KDIM; idx += NTHR) {
        int j = idx / KDIM, k = idx - j * KDIM;
        W2s[j][k] = Who[(jr0 + j) * KDIM + k];
    }
    if (tid < 8) bih_s[tid] = Bih[jh0 + tid];
    if (tid < 4) bho_s[tid] = Bho[jr0 + tid];
    if (tid == 0) bar_flag = 0;

    // ---- t=0 states into output/exchange buffers ----
    for (int idx = tid; idx < 32 * 8; idx += NTHR) {
        int b = b0 + (idx >> 3), jj = idx & 7;
        Hout[(size_t)(b * 1025) * HID_DIM + jh0 + jj] = H0[b * HID_DIM + jh0 + jj];
    }
    for (int idx = tid; idx < 32 * 4; idx += NTHR) {
        int b = b0 + (idx >> 2), jj = idx & 3;
        Rout[(size_t)(b * 1025) * OUT_DIM + jr0 + jj] = R0[b * OUT_DIM + jr0 + jj];
    }
    __syncthreads();   // weights + flag ready

    // A[b*6+c]: c 0..3 = h-col (jh0+ch*4+c), c 4..5 = r-col (jr0+ch*2+c-4)
    float A[24];
#pragma unroll
    for (int i = 0; i < 24; ++i) A[i] = 0.f;

    // ---- prologue: x-dot for it=0 (overlaps other CTAs' init) ----
#pragma unroll
    for (int i = 0; i < 2; ++i) {
        const int k = 4 * lane + 128 * i;
        float4 w[4];
#pragma unroll
        for (int c = 0; c < 4; ++c) w[c] = *(const float4*)&W1s[ch * 4 + c][k];
#pragma unroll
        for (int b = 0; b < 4; ++b) {
            const float4 a = *(const float4*)&X[((size_t)(bb0 + b) * TSTEPS + 0) * IN_DIM + k];
#pragma unroll
            for (int c = 0; c < 4; ++c)
                A[b * 6 + c] += a.x * w[c].x + a.y * w[c].y
                              + a.z * w[c].z + a.w * w[c].w;
        }
    }

    grid_barrier();   // one-time: everyone's H0/R0 copies visible

    for (int it = 0; it <= TSTEPS; ++it) {
        // ---- h[it] feeds BOTH the h-dot (W_ih k=256..767) and r-dot (W_ho k=0..511) ----
#pragma unroll
        for (int i = 0; i < 4; ++i) {
            const int hk = 4 * lane + 128 * i;
            float4 w1[4], w2[2];
#pragma unroll
            for (int c = 0; c < 4; ++c) w1[c] = *(const float4*)&W1s[ch * 4 + c][256 + hk];
#pragma unroll
            for (int c = 0; c < 2; ++c) w2[c] = *(const float4*)&W2s[ch * 2 + c][hk];
#pragma unroll
            for (int b = 0; b < 4; ++b) {
                const float4 a = *(const float4*)&Hout[((size_t)(bb0 + b) * 1025 + it) * HID_DIM + hk];
#pragma unroll
                for (int c = 0; c < 4; ++c)
                    A[b * 6 + c] += a.x * w1[c].x + a.y * w1[c].y
                                  + a.z * w1[c].z + a.w * w1[c].w;
#pragma unroll
                for (int c = 0; c < 2; ++c)
                    A[b * 6 + 4 + c] += a.x * w2[c].x + a.y * w2[c].y
                                      + a.z * w2[c].z + a.w * w2[c].w;
            }
        }

        // ---- r[it-1] contribution (W_ho k = 512..767) ----
        if (it >= 1) {
#pragma unroll
            for (int i = 0; i < 2; ++i) {
                const int rk = 4 * lane + 128 * i;
                float4 w2[2];
#pragma unroll
                for (int c = 0; c < 2; ++c) w2[c] = *(const float4*)&W2s[ch * 2 + c][512 + rk];
#pragma unroll
                for (int b = 0; b < 4; ++b) {
                    const float4 a = *(const float4*)&Rout[((size_t)(bb0 + b) * 1025 + (it - 1)) * OUT_DIM + rk];
#pragma unroll
                    for (int c = 0; c < 2; ++c)
                        A[b * 6 + 4 + c] += a.x * w2[c].x + a.y * w2[c].y
                                          + a.z * w2[c].z + a.w * w2[c].w;
                }
            }
        }

        // ---- transpose-butterfly reduction: 31 shuffles, output L lands on lane L ----
#pragma unroll
        for (int off = 16; off >= 1; off >>= 1) {
#pragma unroll
            for (int i = 0; i < off && i < 24; ++i) {
                const int j = i + off;
                const float vj = (j < 24) ? A[j] : 0.f;
                const float send = (lane & off) ? A[i] : vj;
                const float recv = __shfl_xor_sync(0xffffffffu, send, off);
                const float keep = (lane & off) ? vj : A[i];
                A[i] = keep + recv;
            }
        }

        // ---- bias + relu + store ----
        if (lane < 24) {
            const int bl = lane / 6;
            const int c  = lane % 6;
            if (c < 4) {
                if (it < TSTEPS) {
                    const float v = fmaxf(A[0] + bih_s[ch * 4 + c], 0.f);
                    Hout[((size_t)(bb0 + bl) * 1025 + (it + 1)) * HID_DIM + jh0 + ch * 4 + c] = v;
                }
            } else {
                if (it >= 1) {
                    const int cc = c - 4;
                    const float v = fmaxf(A[0] + bho_s[ch * 2 + cc], 0.f);
                    Rout[((size_t)(bb0 + bl) * 1025 + it) * OUT_DIM + jr0 + ch * 2 + cc] = v;
                }
            }
        }

        if (it == TSTEPS) break;          // last outputs stored; no more exchange

        __syncthreads();                  // CTA-wide: all stores issued
        if (tid == 0) red_release_add1(cnt);   // arrive (release: orders CTA's stores)

        // ---- pre-release window: zero accs and fold in x-dot for it+1 ----
#pragma unroll
        for (int i = 0; i < 24; ++i) A[i] = 0.f;
        const int xt = it + 1;
        if (xt < TSTEPS) {
#pragma unroll
            for (int i = 0; i < 2; ++i) {
                const int k = 4 * lane + 128 * i;
                float4 w[4];
#pragma unroll
                for (int c = 0; c < 4; ++c) w[c] = *(const float4*)&W1s[ch * 4 + c][k];
#pragma unroll
                for (int b = 0; b < 4; ++b) {
                    const float4 a = *(const float4*)&X[((size_t)(bb0 + b) * TSTEPS + xt) * IN_DIM + k];
#pragma unroll
                    for (int c = 0; c < 4; ++c)
                        A[b * 6 + c] += a.x * w[c].x + a.y * w[c].y
                                      + a.z * w[c].z + a.w * w[c].w;
                }
            }
        }

        // ---- wait for this half's epoch: t0 polls L2, relays via smem flag ----
        const int epoch = it + 1;
        if (tid == 0) {
            const unsigned tgt = 64u * (unsigned)epoch;
            while ((int)(ld_acquire_u32(cnt) - tgt) < 0) {}
            bar_flag = epoch;
        } else if (lane == 0) {
            while (bar_flag < epoch) {}
        }
        __syncwarp();
    }

    // ---- reset epoch counters for the next graph replay ----
    grid_barrier();                       // all polls done grid-wide
    if (cta < 2 && tid == 0) g_cnt[cta * 64] = 0;
}

extern "C" void kernel_launch(void* const* d_in, const int* in_sizes, int n_in,
                              void* d_out, int out_size) {
    const float* X   = (const float*)d_in[0];
    const float* H0  = (const float*)d_in[1];
    const float* R0  = (const float*)d_in[2];
    const float* Wih = (const float*)d_in[3];
    const float* Bih = (const float*)d_in[4];
    const float* Who = (const float*)d_in[5];
    const float* Bho = (const float*)d_in[6];

    float* Rout = (float*)d_out;                                   // [64][1025][256]
    float* Hout = (float*)d_out + (size_t)BATCH * 1025 * OUT_DIM;  // [64][1025][512]

    rnn_persistent_kernel<<<NCTA, NTHR>>>(X, H0, R0, Wih, Bih, Who, Bho, Rout, Hout);
}